// round 1
// baseline (speedup 1.0000x reference)
#include <cuda_runtime.h>
#include <math.h>

#define B_  2
#define S_  2048
#define H_  8
#define D_  64
#define DM_ 512
#define W_  128

// Scratch (device globals — no allocation allowed)
__device__ float g_q[B_*H_*S_*D_];
__device__ float g_k[B_*H_*S_*D_];
__device__ float g_v[B_*H_*S_*D_];
__device__ float g_attn[B_*S_*DM_];

// ---------------------------------------------------------------------------
// GEMM: C[4096x512] = A[4096x512] * W[512x512]
// BM=BN=64, BK=16, 256 threads, 4x4 micro-tile per thread.
// ---------------------------------------------------------------------------

// QKV projection: blockIdx.z selects weight & destination; output written in
// head-major layout [b][h][s][d].
__global__ void __launch_bounds__(256) gemm_qkv_k(
    const float* __restrict__ X,
    const float* __restrict__ Wq,
    const float* __restrict__ Wk,
    const float* __restrict__ Wv)
{
    const float* Wt = (blockIdx.z == 0) ? Wq : (blockIdx.z == 1 ? Wk : Wv);
    float* Out      = (blockIdx.z == 0) ? g_q : (blockIdx.z == 1 ? g_k : g_v);

    __shared__ float As[16][65];   // transposed A tile, padded
    __shared__ float Bs[16][64];

    const int tid = threadIdx.x;
    const int tn = tid & 15, tm = tid >> 4;
    const int m0 = blockIdx.y << 6;
    const int n0 = blockIdx.x << 6;
    const int ar = tid >> 2, ac = (tid & 3) << 2;
    const int br = tid >> 4, bc = (tid & 15) << 2;

    float acc[4][4] = {};

    for (int k0 = 0; k0 < DM_; k0 += 16) {
        float4 av = *(const float4*)(X + (m0 + ar) * DM_ + k0 + ac);
        As[ac + 0][ar] = av.x;
        As[ac + 1][ar] = av.y;
        As[ac + 2][ar] = av.z;
        As[ac + 3][ar] = av.w;
        *(float4*)(&Bs[br][bc]) = *(const float4*)(Wt + (k0 + br) * DM_ + n0 + bc);
        __syncthreads();
#pragma unroll
        for (int kk = 0; kk < 16; kk++) {
            float a0 = As[kk][tm * 4 + 0];
            float a1 = As[kk][tm * 4 + 1];
            float a2 = As[kk][tm * 4 + 2];
            float a3 = As[kk][tm * 4 + 3];
            float4 bv = *(float4*)(&Bs[kk][tn * 4]);
            acc[0][0] += a0 * bv.x; acc[0][1] += a0 * bv.y; acc[0][2] += a0 * bv.z; acc[0][3] += a0 * bv.w;
            acc[1][0] += a1 * bv.x; acc[1][1] += a1 * bv.y; acc[1][2] += a1 * bv.z; acc[1][3] += a1 * bv.w;
            acc[2][0] += a2 * bv.x; acc[2][1] += a2 * bv.y; acc[2][2] += a2 * bv.z; acc[2][3] += a2 * bv.w;
            acc[3][0] += a3 * bv.x; acc[3][1] += a3 * bv.y; acc[3][2] += a3 * bv.z; acc[3][3] += a3 * bv.w;
        }
        __syncthreads();
    }

    // Store, remapped to head-major. Block covers one head (BN=64=head dim).
    const int h = blockIdx.x;
#pragma unroll
    for (int i = 0; i < 4; i++) {
        int m = m0 + tm * 4 + i;
        int b = m >> 11;
        int s = m & (S_ - 1);
        float4 o = make_float4(acc[i][0], acc[i][1], acc[i][2], acc[i][3]);
        *(float4*)(Out + (((b * H_ + h) * S_) + s) * D_ + tn * 4) = o;
    }
}

// Output projection: C = g_attn * Wo, plain row-major store to d_out.
__global__ void __launch_bounds__(256) gemm_out_k(
    const float* __restrict__ Wo,
    float* __restrict__ C)
{
    const float* A = g_attn;
    __shared__ float As[16][65];
    __shared__ float Bs[16][64];

    const int tid = threadIdx.x;
    const int tn = tid & 15, tm = tid >> 4;
    const int m0 = blockIdx.y << 6;
    const int n0 = blockIdx.x << 6;
    const int ar = tid >> 2, ac = (tid & 3) << 2;
    const int br = tid >> 4, bc = (tid & 15) << 2;

    float acc[4][4] = {};

    for (int k0 = 0; k0 < DM_; k0 += 16) {
        float4 av = *(const float4*)(A + (m0 + ar) * DM_ + k0 + ac);
        As[ac + 0][ar] = av.x;
        As[ac + 1][ar] = av.y;
        As[ac + 2][ar] = av.z;
        As[ac + 3][ar] = av.w;
        *(float4*)(&Bs[br][bc]) = *(const float4*)(Wo + (k0 + br) * DM_ + n0 + bc);
        __syncthreads();
#pragma unroll
        for (int kk = 0; kk < 16; kk++) {
            float a0 = As[kk][tm * 4 + 0];
            float a1 = As[kk][tm * 4 + 1];
            float a2 = As[kk][tm * 4 + 2];
            float a3 = As[kk][tm * 4 + 3];
            float4 bv = *(float4*)(&Bs[kk][tn * 4]);
            acc[0][0] += a0 * bv.x; acc[0][1] += a0 * bv.y; acc[0][2] += a0 * bv.z; acc[0][3] += a0 * bv.w;
            acc[1][0] += a1 * bv.x; acc[1][1] += a1 * bv.y; acc[1][2] += a1 * bv.z; acc[1][3] += a1 * bv.w;
            acc[2][0] += a2 * bv.x; acc[2][1] += a2 * bv.y; acc[2][2] += a2 * bv.z; acc[2][3] += a2 * bv.w;
            acc[3][0] += a3 * bv.x; acc[3][1] += a3 * bv.y; acc[3][2] += a3 * bv.z; acc[3][3] += a3 * bv.w;
        }
        __syncthreads();
    }

#pragma unroll
    for (int i = 0; i < 4; i++) {
        int m = m0 + tm * 4 + i;
        float4 o = make_float4(acc[i][0], acc[i][1], acc[i][2], acc[i][3]);
        *(float4*)(C + m * DM_ + n0 + tn * 4) = o;
    }
}

// ---------------------------------------------------------------------------
// Sliding-window attention.
// Block = (64-query tile, head, batch). Key band per tile: 192 keys
// [s0-127, s0+63]; query row i (tile coords) attends band j in [i, i+127],
// clipped so the global key index s0-127+j >= 0.
//
// SMEM (dynamic, 114944 B):
//   Qst [64][65]   transposed Q (d-major)            floats [0, 4160)
//   Ks  [192][64]  keys, natural layout              floats [4160, 16448)
//   Vs  [192][64]  values, natural layout            floats [16448, 28736)
//   Ss  [64][193]  scores/probs (aliases Qst+Ks after phase 1)
// ---------------------------------------------------------------------------
#define ATT_SMEM_FLOATS (64*65 + 192*64 + 192*64)
#define ATT_SMEM_BYTES  (ATT_SMEM_FLOATS * 4)

__global__ void __launch_bounds__(256) attn_k()
{
    extern __shared__ float sm[];
    float* Qst = sm;               // [64][65]  (d-major)
    float* Ks  = sm + 64 * 65;     // [192][64]
    float* Vs  = Ks + 192 * 64;    // [192][64]
    float* Ss  = sm;               // [64][193] alias (phase >= 2)

    const int tid = threadIdx.x;
    const int s0 = blockIdx.x << 6;
    const int h  = blockIdx.y;
    const int b  = blockIdx.z;
    const int base = ((b * H_ + h) * S_) * D_;

    // ---- load Q (transposed into Qst) ----
#pragma unroll
    for (int it = 0; it < 4; it++) {
        int idx = tid + it * 256;
        int qq = idx >> 4;
        int dc = (idx & 15) << 2;
        float4 qv = *(const float4*)(g_q + base + (s0 + qq) * D_ + dc);
        Qst[(dc + 0) * 65 + qq] = qv.x;
        Qst[(dc + 1) * 65 + qq] = qv.y;
        Qst[(dc + 2) * 65 + qq] = qv.z;
        Qst[(dc + 3) * 65 + qq] = qv.w;
    }
    // ---- load K / V bands (zero-fill out-of-range low side) ----
#pragma unroll
    for (int it = 0; it < 12; it++) {
        int idx = tid + it * 256;
        int jr = idx >> 4;
        int dc = (idx & 15) << 2;
        int kg = s0 - (W_ - 1) + jr;
        float4 kv = make_float4(0.f, 0.f, 0.f, 0.f);
        float4 vv = make_float4(0.f, 0.f, 0.f, 0.f);
        if (kg >= 0) {
            kv = *(const float4*)(g_k + base + kg * D_ + dc);
            vv = *(const float4*)(g_v + base + kg * D_ + dc);
        }
        *(float4*)(Ks + jr * 64 + dc) = kv;
        *(float4*)(Vs + jr * 64 + dc) = vv;
    }
    __syncthreads();

    // ---- phase 1: S[64][192] = Q * K^T  (4 rows x 12 cols per thread) ----
    const int qg = tid & 15;   // q micro-row group (lanes vary -> conflict-free via pad)
    const int jg = tid >> 4;   // j micro-col group (broadcast reads of K)
    const int jb = jg * 12;
    float acc[4][12];
#pragma unroll
    for (int r = 0; r < 4; r++)
#pragma unroll
        for (int u = 0; u < 12; u++) acc[r][u] = 0.f;

#pragma unroll 8
    for (int d = 0; d < 64; d++) {
        float a0 = Qst[d * 65 + qg * 4 + 0];
        float a1 = Qst[d * 65 + qg * 4 + 1];
        float a2 = Qst[d * 65 + qg * 4 + 2];
        float a3 = Qst[d * 65 + qg * 4 + 3];
#pragma unroll
        for (int u = 0; u < 12; u++) {
            float kv = Ks[(jb + u) * 64 + d];
            acc[0][u] += a0 * kv;
            acc[1][u] += a1 * kv;
            acc[2][u] += a2 * kv;
            acc[3][u] += a3 * kv;
        }
    }
    __syncthreads();   // Qst/Ks dead; Ss may now overwrite them

    // ---- mask band + scale, write to Ss ----
#pragma unroll
    for (int r = 0; r < 4; r++) {
        int i  = qg * 4 + r;
        int lo = (i > (W_ - 1) - s0) ? i : ((W_ - 1) - s0);
        int hi = i + (W_ - 1);
#pragma unroll
        for (int u = 0; u < 12; u++) {
            int j = jb + u;
            float sv = (j >= lo && j <= hi) ? acc[r][u] * 0.125f : -3.0e38f;
            Ss[i * 193 + j] = sv;
        }
    }
    __syncthreads();

    // ---- phase 2: row softmax (warp handles 8 rows) ----
    {
        const int w = tid >> 5, lane = tid & 31;
#pragma unroll
        for (int rr = 0; rr < 8; rr++) {
            float* row = Ss + ((w << 3) + rr) * 193;
            float m = -3.0e38f;
#pragma unroll
            for (int c = lane; c < 192; c += 32) m = fmaxf(m, row[c]);
#pragma unroll
            for (int msk = 16; msk >= 1; msk >>= 1)
                m = fmaxf(m, __shfl_xor_sync(0xffffffffu, m, msk));
            float ssum = 0.f;
#pragma unroll
            for (int c = lane; c < 192; c += 32) {
                float e = __expf(row[c] - m);
                row[c] = e;
                ssum += e;
            }
#pragma unroll
            for (int msk = 16; msk >= 1; msk >>= 1)
                ssum += __shfl_xor_sync(0xffffffffu, ssum, msk);
            float inv = 1.0f / ssum;
#pragma unroll
            for (int c = lane; c < 192; c += 32) row[c] *= inv;
        }
    }
    __syncthreads();

    // ---- phase 3: O[64][64] = P * V  (4 rows x 4 d-cols per thread) ----
    {
        const int qg3 = tid & 15;
        const int dg  = tid >> 4;
        float o[4][4];
#pragma unroll
        for (int r = 0; r < 4; r++)
#pragma unroll
            for (int c = 0; c < 4; c++) o[r][c] = 0.f;

#pragma unroll 8
        for (int j = 0; j < 192; j++) {
            float4 vv = *(float4*)(Vs + j * 64 + dg * 4);
#pragma unroll
            for (int r = 0; r < 4; r++) {
                float p = Ss[(qg3 * 4 + r) * 193 + j];
                o[r][0] += p * vv.x;
                o[r][1] += p * vv.y;
                o[r][2] += p * vv.z;
                o[r][3] += p * vv.w;
            }
        }
#pragma unroll
        for (int r = 0; r < 4; r++) {
            int q = qg3 * 4 + r;
            float4 ov = make_float4(o[r][0], o[r][1], o[r][2], o[r][3]);
            *(float4*)(g_attn + (b * S_ + s0 + q) * DM_ + h * D_ + dg * 4) = ov;
        }
    }
}

// ---------------------------------------------------------------------------
extern "C" void kernel_launch(void* const* d_in, const int* in_sizes, int n_in,
                              void* d_out, int out_size)
{
    const float* x  = (const float*)d_in[0];
    const float* Wq = (const float*)d_in[1];
    const float* Wk = (const float*)d_in[2];
    const float* Wv = (const float*)d_in[3];
    const float* Wo = (const float*)d_in[4];
    float* out = (float*)d_out;

    // QKV projections (z selects weight)
    gemm_qkv_k<<<dim3(DM_ / 64, (B_ * S_) / 64, 3), 256>>>(x, Wq, Wk, Wv);

    // Sliding-window attention
    cudaFuncSetAttribute(attn_k, cudaFuncAttributeMaxDynamicSharedMemorySize,
                         ATT_SMEM_BYTES);
    attn_k<<<dim3(S_ / 64, H_, B_), 256, ATT_SMEM_BYTES>>>();

    // Output projection
    gemm_out_k<<<dim3(DM_ / 64, (B_ * S_) / 64), 256>>>(Wo, out);
}

// round 2
// speedup vs baseline: 1.3047x; 1.3047x over previous
#include <cuda_runtime.h>
#include <math.h>

#define B_  2
#define S_  2048
#define H_  8
#define D_  64
#define DM_ 512
#define W_  128

typedef unsigned long long ull;

// Scratch (device globals — no allocation allowed)
__device__ float g_q[B_*H_*S_*D_];
__device__ float g_k[B_*H_*S_*D_];
__device__ float g_v[B_*H_*S_*D_];
__device__ float g_attn[B_*S_*DM_];

// ---- packed fp32x2 helpers (sm_103a) --------------------------------------
__device__ __forceinline__ ull pack2(float lo, float hi) {
    ull r; asm("mov.b64 %0, {%1, %2};" : "=l"(r) : "f"(lo), "f"(hi)); return r;
}
__device__ __forceinline__ void fma2(ull& d, ull a, ull b) {
    asm("fma.rn.f32x2 %0, %1, %2, %0;" : "+l"(d) : "l"(a), "l"(b));
}
__device__ __forceinline__ float2 unpk(ull v) {
    float2 f; asm("mov.b64 {%0, %1}, %2;" : "=f"(f.x), "=f"(f.y) : "l"(v)); return f;
}

// ---------------------------------------------------------------------------
// GEMM core: C[4096x512] = A[4096x512] * W[512x512]
// BM=BN=128, BK=16, 256 threads, 8x8 micro-tile, f32x2 packed FMA.
// ---------------------------------------------------------------------------
#define GEMM_BODY(APTR, WPTR)                                                  \
    __shared__ float As[16 * 132];   /* transposed [k][m], stride 132 */       \
    __shared__ float Bs[16 * 128];                                             \
    const int tid = threadIdx.x;                                               \
    const int tr = tid >> 4, tc = tid & 15;                                    \
    const int m0 = blockIdx.y << 7;                                            \
    const int n0 = blockIdx.x << 7;                                            \
    ull acc[8][4];                                                             \
    _Pragma("unroll")                                                          \
    for (int r = 0; r < 8; r++)                                                \
        _Pragma("unroll")                                                      \
        for (int c = 0; c < 4; c++) acc[r][c] = 0ull;                          \
    for (int k0 = 0; k0 < DM_; k0 += 16) {                                     \
        _Pragma("unroll")                                                      \
        for (int i = 0; i < 2; i++) {                                          \
            int idx = tid + (i << 8);                                          \
            int arow = idx >> 2, acol = (idx & 3) << 2;                        \
            float4 av = *(const float4*)(APTR + (m0 + arow) * DM_ + k0 + acol);\
            As[(acol + 0) * 132 + arow] = av.x;                                \
            As[(acol + 1) * 132 + arow] = av.y;                                \
            As[(acol + 2) * 132 + arow] = av.z;                                \
            As[(acol + 3) * 132 + arow] = av.w;                                \
            int brow = idx >> 5, bcol = (idx & 31) << 2;                       \
            *(float4*)(&Bs[brow * 128 + bcol]) =                               \
                *(const float4*)(WPTR + (k0 + brow) * DM_ + n0 + bcol);        \
        }                                                                      \
        __syncthreads();                                                       \
        _Pragma("unroll")                                                      \
        for (int kk = 0; kk < 16; kk++) {                                      \
            float4 alo = *(float4*)(&As[kk * 132 + tr * 4]);                   \
            float4 ahi = *(float4*)(&As[kk * 132 + 64 + tr * 4]);              \
            ull b0 = *(ull*)(&Bs[kk * 128 + tc * 4]);                          \
            ull b1 = *(ull*)(&Bs[kk * 128 + tc * 4 + 2]);                      \
            ull b2 = *(ull*)(&Bs[kk * 128 + 64 + tc * 4]);                     \
            ull b3 = *(ull*)(&Bs[kk * 128 + 64 + tc * 4 + 2]);                 \
            ull aP[8];                                                         \
            aP[0] = pack2(alo.x, alo.x); aP[1] = pack2(alo.y, alo.y);          \
            aP[2] = pack2(alo.z, alo.z); aP[3] = pack2(alo.w, alo.w);          \
            aP[4] = pack2(ahi.x, ahi.x); aP[5] = pack2(ahi.y, ahi.y);          \
            aP[6] = pack2(ahi.z, ahi.z); aP[7] = pack2(ahi.w, ahi.w);          \
            _Pragma("unroll")                                                  \
            for (int r = 0; r < 8; r++) {                                      \
                fma2(acc[r][0], aP[r], b0);                                    \
                fma2(acc[r][1], aP[r], b1);                                    \
                fma2(acc[r][2], aP[r], b2);                                    \
                fma2(acc[r][3], aP[r], b3);                                    \
            }                                                                  \
        }                                                                      \
        __syncthreads();                                                       \
    }

// QKV projection: blockIdx.z selects weight; output head-major [b][h][s][d].
__global__ void __launch_bounds__(256, 2) gemm_qkv_k(
    const float* __restrict__ X,
    const float* __restrict__ Wq,
    const float* __restrict__ Wk,
    const float* __restrict__ Wv)
{
    const float* Wt = (blockIdx.z == 0) ? Wq : (blockIdx.z == 1 ? Wk : Wv);
    float* Out      = (blockIdx.z == 0) ? g_q : (blockIdx.z == 1 ? g_k : g_v);

    GEMM_BODY(X, Wt)

#pragma unroll
    for (int ri = 0; ri < 8; ri++) {
        int m = m0 + tr * 4 + ri + ((ri >= 4) ? 60 : 0);
        int b = m >> 11;
        int s = m & (S_ - 1);
#pragma unroll
        for (int half = 0; half < 2; half++) {
            int ncol = n0 + half * 64 + tc * 4;
            int h = ncol >> 6, d = ncol & 63;
            float2 p0 = unpk(acc[ri][half * 2]);
            float2 p1 = unpk(acc[ri][half * 2 + 1]);
            float4 o = make_float4(p0.x, p0.y, p1.x, p1.y);
            *(float4*)(Out + (((b * H_ + h) * S_) + s) * D_ + d) = o;
        }
    }
}

// Output projection: C = g_attn * Wo, row-major store.
__global__ void __launch_bounds__(256, 2) gemm_out_k(
    const float* __restrict__ Wo,
    float* __restrict__ C)
{
    const float* A = g_attn;
    GEMM_BODY(A, Wo)

#pragma unroll
    for (int ri = 0; ri < 8; ri++) {
        int m = m0 + tr * 4 + ri + ((ri >= 4) ? 60 : 0);
#pragma unroll
        for (int half = 0; half < 2; half++) {
            int ncol = n0 + half * 64 + tc * 4;
            float2 p0 = unpk(acc[ri][half * 2]);
            float2 p1 = unpk(acc[ri][half * 2 + 1]);
            float4 o = make_float4(p0.x, p0.y, p1.x, p1.y);
            *(float4*)(C + m * DM_ + ncol) = o;
        }
    }
}

// ---------------------------------------------------------------------------
// Sliding-window attention, f32x2 packed.
// Block = (64-query tile, head, batch). Band of 192 keys [s0-127, s0+63].
// SMEM: Qs[64][66] | Ks[192][64] | Vs[192][64];  Ss[64][193] aliases Qs+Ks.
// ---------------------------------------------------------------------------
#define ATT_SMEM_FLOATS (64*66 + 192*64 + 192*64)
#define ATT_SMEM_BYTES  (ATT_SMEM_FLOATS * 4)

__global__ void __launch_bounds__(256, 1) attn_k()
{
    extern __shared__ float sm[];
    float* Qs = sm;                 // [64][66]
    float* Ks = sm + 64 * 66;       // [192][64]
    float* Vs = Ks + 192 * 64;      // [192][64]
    float* Ss = sm;                 // [64][193] alias over Qs+Ks

    const int tid = threadIdx.x;
    const int s0 = blockIdx.x << 6;
    const int h  = blockIdx.y;
    const int b  = blockIdx.z;
    const int base = ((b * H_ + h) * S_) * D_;

    // ---- load Q (natural [q][d], stride 66) ----
#pragma unroll
    for (int it = 0; it < 4; it++) {
        int idx = tid + it * 256;
        int qq = idx >> 4;
        int dc = (idx & 15) << 2;
        float4 qv = *(const float4*)(g_q + base + (s0 + qq) * D_ + dc);
        Qs[qq * 66 + dc + 0] = qv.x;
        Qs[qq * 66 + dc + 1] = qv.y;
        Qs[qq * 66 + dc + 2] = qv.z;
        Qs[qq * 66 + dc + 3] = qv.w;
    }
    // ---- load K / V band (zero-fill below 0) ----
#pragma unroll
    for (int it = 0; it < 12; it++) {
        int idx = tid + it * 256;
        int jr = idx >> 4;
        int dc = (idx & 15) << 2;
        int kg = s0 - (W_ - 1) + jr;
        float4 kv = make_float4(0.f, 0.f, 0.f, 0.f);
        float4 vv = make_float4(0.f, 0.f, 0.f, 0.f);
        if (kg >= 0) {
            kv = *(const float4*)(g_k + base + kg * D_ + dc);
            vv = *(const float4*)(g_v + base + kg * D_ + dc);
        }
        *(float4*)(Ks + jr * 64 + dc) = kv;
        *(float4*)(Vs + jr * 64 + dc) = vv;
    }
    __syncthreads();

    // ---- phase 1: S = Q K^T, f32x2 packed along d ----
    const int qg = tid & 15;        // q = qg + 16*r  (conflict-free lanes)
    const int jg = tid >> 4;
    const int jb = jg * 12;
    ull acc2[4][12];
#pragma unroll
    for (int r = 0; r < 4; r++)
#pragma unroll
        for (int u = 0; u < 12; u++) acc2[r][u] = 0ull;

#pragma unroll 4
    for (int d = 0; d < 64; d += 2) {
        ull qv[4];
#pragma unroll
        for (int r = 0; r < 4; r++)
            qv[r] = *(ull*)(&Qs[(qg + 16 * r) * 66 + d]);
#pragma unroll
        for (int u = 0; u < 12; u++) {
            ull kv = *(ull*)(&Ks[(jb + u) * 64 + d]);
            fma2(acc2[0][u], qv[0], kv);
            fma2(acc2[1][u], qv[1], kv);
            fma2(acc2[2][u], qv[2], kv);
            fma2(acc2[3][u], qv[3], kv);
        }
    }
    __syncthreads();   // Qs/Ks dead; Ss may overwrite

    // ---- mask + scale, write Ss ----
#pragma unroll
    for (int r = 0; r < 4; r++) {
        int i  = qg + 16 * r;
        int lo = (i > (W_ - 1) - s0) ? i : ((W_ - 1) - s0);
        int hi = i + (W_ - 1);
#pragma unroll
        for (int u = 0; u < 12; u++) {
            int j = jb + u;
            float2 f = unpk(acc2[r][u]);
            float sv = (f.x + f.y) * 0.125f;
            Ss[i * 193 + j] = (j >= lo && j <= hi) ? sv : -3.0e38f;
        }
    }
    __syncthreads();

    // ---- phase 2: row softmax (warp per 8 rows) ----
    {
        const int w = tid >> 5, lane = tid & 31;
#pragma unroll
        for (int rr = 0; rr < 8; rr++) {
            float* row = Ss + ((w << 3) + rr) * 193;
            float m = -3.0e38f;
#pragma unroll
            for (int c = lane; c < 192; c += 32) m = fmaxf(m, row[c]);
#pragma unroll
            for (int msk = 16; msk >= 1; msk >>= 1)
                m = fmaxf(m, __shfl_xor_sync(0xffffffffu, m, msk));
            float ssum = 0.f;
#pragma unroll
            for (int c = lane; c < 192; c += 32) {
                float e = __expf(row[c] - m);
                row[c] = e;
                ssum += e;
            }
#pragma unroll
            for (int msk = 16; msk >= 1; msk >>= 1)
                ssum += __shfl_xor_sync(0xffffffffu, ssum, msk);
            float inv = 1.0f / ssum;
#pragma unroll
            for (int c = lane; c < 192; c += 32) row[c] *= inv;
        }
    }
    __syncthreads();

    // ---- phase 3: O = P V, f32x2 packed along head-dim ----
    {
        const int qg3 = tid & 15;   // q = qg3 + 16*r
        const int dg  = tid >> 4;   // d block = dg*4
        ull o2[4][2];
#pragma unroll
        for (int r = 0; r < 4; r++) { o2[r][0] = 0ull; o2[r][1] = 0ull; }

#pragma unroll 4
        for (int j = 0; j < 192; j++) {
            float4 vv = *(float4*)(Vs + j * 64 + dg * 4);
            ull v0 = pack2(vv.x, vv.y);
            ull v1 = pack2(vv.z, vv.w);
#pragma unroll
            for (int r = 0; r < 4; r++) {
                float p = Ss[(qg3 + 16 * r) * 193 + j];
                ull pp = pack2(p, p);
                fma2(o2[r][0], pp, v0);
                fma2(o2[r][1], pp, v1);
            }
        }
#pragma unroll
        for (int r = 0; r < 4; r++) {
            int q = qg3 + 16 * r;
            float2 p0 = unpk(o2[r][0]);
            float2 p1 = unpk(o2[r][1]);
            float4 ov = make_float4(p0.x, p0.y, p1.x, p1.y);
            *(float4*)(g_attn + (b * S_ + s0 + q) * DM_ + h * D_ + dg * 4) = ov;
        }
    }
}

// ---------------------------------------------------------------------------
extern "C" void kernel_launch(void* const* d_in, const int* in_sizes, int n_in,
                              void* d_out, int out_size)
{
    const float* x  = (const float*)d_in[0];
    const float* Wq = (const float*)d_in[1];
    const float* Wk = (const float*)d_in[2];
    const float* Wv = (const float*)d_in[3];
    const float* Wo = (const float*)d_in[4];
    float* out = (float*)d_out;

    gemm_qkv_k<<<dim3(DM_ / 128, (B_ * S_) / 128, 3), 256>>>(x, Wq, Wk, Wv);

    cudaFuncSetAttribute(attn_k, cudaFuncAttributeMaxDynamicSharedMemorySize,
                         ATT_SMEM_BYTES);
    attn_k<<<dim3(S_ / 64, H_, B_), 256, ATT_SMEM_BYTES>>>();

    gemm_out_k<<<dim3(DM_ / 128, (B_ * S_) / 128), 256>>>(Wo, out);
}

// round 4
// speedup vs baseline: 2.0860x; 1.5989x over previous
#include <cuda_runtime.h>
#include <cuda_bf16.h>
#include <math.h>
#include <stdint.h>

#define B_  2
#define S_  2048
#define H_  8
#define D_  64
#define DM_ 512
#define W_  128

typedef unsigned long long ull;

// ---------------- scratch (device globals; no allocation) ------------------
__device__ float g_q[B_*H_*S_*D_];
__device__ float g_k[B_*H_*S_*D_];
__device__ float g_v[B_*H_*S_*D_];
__device__ float g_attn[B_*S_*DM_];
// split-bf16 operands
__device__ __nv_bfloat16 g_ah[B_*S_*DM_];     // A hi (X, later attn-out)
__device__ __nv_bfloat16 g_al[B_*S_*DM_];     // A lo
__device__ __nv_bfloat16 g_wh[4*DM_*DM_];     // W^T hi: rows 0..1535 = Wq,Wk,Wv; 1536.. Wo
__device__ __nv_bfloat16 g_wl[4*DM_*DM_];     // W^T lo

// ---------------- fp32x2 helpers (attention kernel) ------------------------
__device__ __forceinline__ ull pack2(float lo, float hi) {
    ull r; asm("mov.b64 %0, {%1, %2};" : "=l"(r) : "f"(lo), "f"(hi)); return r;
}
__device__ __forceinline__ void fma2(ull& d, ull a, ull b) {
    asm("fma.rn.f32x2 %0, %1, %2, %0;" : "+l"(d) : "l"(a), "l"(b));
}
__device__ __forceinline__ float2 unpk(ull v) {
    float2 f; asm("mov.b64 {%0, %1}, %2;" : "=f"(f.x), "=f"(f.y) : "l"(v)); return f;
}

__device__ __forceinline__ uint32_t smem_u32(const void* p) {
    uint32_t a;
    asm("{ .reg .u64 t; cvta.to.shared.u64 t, %1; cvt.u32.u64 %0, t; }" : "=r"(a) : "l"(p));
    return a;
}

// ---------------- mma.sync building blocks (plain sm_103 PTX) --------------
#define LDSM4(r, addr) \
    asm volatile("ldmatrix.sync.aligned.m8n8.x4.shared.b16 {%0,%1,%2,%3}, [%4];" \
        : "=r"((r)[0]), "=r"((r)[1]), "=r"((r)[2]), "=r"((r)[3]) : "r"(addr))

#define MMA16816(c, a, b0, b1) \
    asm volatile("mma.sync.aligned.m16n8k16.row.col.f32.bf16.bf16.f32 " \
        "{%0,%1,%2,%3}, {%4,%5,%6,%7}, {%8,%9}, {%0,%1,%2,%3};" \
        : "+f"((c)[0]), "+f"((c)[1]), "+f"((c)[2]), "+f"((c)[3]) \
        : "r"((a)[0]), "r"((a)[1]), "r"((a)[2]), "r"((a)[3]), "r"(b0), "r"(b1))

__device__ __forceinline__ void cpa16(uint32_t s, const __nv_bfloat16* g) {
    asm volatile("cp.async.ca.shared.global [%0], [%1], 16;" :: "r"(s), "l"(g));
}

// ---------------------------------------------------------------------------
// Conversion kernels
// ---------------------------------------------------------------------------
__global__ void __launch_bounds__(256) conv_split_k(const float* __restrict__ X,
                                                    int use_attn)
{
    const float* src = use_attn ? g_attn : X;
    int i = (blockIdx.x * 256 + threadIdx.x) * 4;
    float4 v = *(const float4*)(src + i);
    __nv_bfloat16 h0 = __float2bfloat16(v.x);
    __nv_bfloat16 h1 = __float2bfloat16(v.y);
    __nv_bfloat16 h2 = __float2bfloat16(v.z);
    __nv_bfloat16 h3 = __float2bfloat16(v.w);
    __nv_bfloat16 l0 = __float2bfloat16(v.x - __bfloat162float(h0));
    __nv_bfloat16 l1 = __float2bfloat16(v.y - __bfloat162float(h1));
    __nv_bfloat16 l2 = __float2bfloat16(v.z - __bfloat162float(h2));
    __nv_bfloat16 l3 = __float2bfloat16(v.w - __bfloat162float(h3));
    *(__nv_bfloat162*)(g_ah + i)     = __nv_bfloat162(h0, h1);
    *(__nv_bfloat162*)(g_ah + i + 2) = __nv_bfloat162(h2, h3);
    *(__nv_bfloat162*)(g_al + i)     = __nv_bfloat162(l0, l1);
    *(__nv_bfloat162*)(g_al + i + 2) = __nv_bfloat162(l2, l3);
}

__global__ void __launch_bounds__(256) conv_w_k(const float* __restrict__ Wq,
                                                const float* __restrict__ Wk,
                                                const float* __restrict__ Wv,
                                                const float* __restrict__ Wo)
{
    const float* Wsrc = (blockIdx.z == 0) ? Wq : (blockIdx.z == 1 ? Wk :
                        (blockIdx.z == 2 ? Wv : Wo));
    __shared__ float t[32][33];
    int bn = blockIdx.x * 32;
    int bk = blockIdx.y * 32;
    int lx = threadIdx.x & 31, ly = threadIdx.x >> 5;
#pragma unroll
    for (int i = 0; i < 32; i += 8)
        t[ly + i][lx] = Wsrc[(bk + ly + i) * DM_ + bn + lx];
    __syncthreads();
    int rowbase = blockIdx.z * DM_;
#pragma unroll
    for (int i = 0; i < 32; i += 8) {
        int r = ly + i;
        float x = t[lx][r];
        __nv_bfloat16 h = __float2bfloat16(x);
        __nv_bfloat16 l = __float2bfloat16(x - __bfloat162float(h));
        long idx = (long)(rowbase + bn + r) * DM_ + bk + lx;
        g_wh[idx] = h;
        g_wl[idx] = l;
    }
}

// ---------------------------------------------------------------------------
// mma.sync split-bf16 GEMM: per CTA M=128, N=128, K=512 (16 chunks of 32).
// smem stage (40960B): Ah[128][40] | Al | Bh | Bl  (bf16, 80B row stride).
// Double buffered: 81920 B total.
// ---------------------------------------------------------------------------
#define GSM_BYTES (2 * 40960)

__device__ __forceinline__ void stage(uint32_t sb, int st, int m0, int nbase, int k0)
{
    const int tid = threadIdx.x;
#pragma unroll
    for (int i = 0; i < 2; i++) {
        int u = tid + (i << 8);
        int r = u >> 2, seg = u & 3;
        uint32_t so = sb + st * 40960 + r * 80 + seg * 16;
        long ga = (long)(m0 + r) * DM_ + k0 + seg * 8;
        long gb = (long)(nbase + r) * DM_ + k0 + seg * 8;
        cpa16(so,         g_ah + ga);
        cpa16(so + 10240, g_al + ga);
        cpa16(so + 20480, g_wh + gb);
        cpa16(so + 30720, g_wl + gb);
    }
    asm volatile("cp.async.commit_group;" ::: "memory");
}

__device__ __forceinline__ void compute_chunk(uint32_t sb, int st, float acc[2][8][4])
{
    const int lane = threadIdx.x & 31, w = threadIdx.x >> 5;
    const int wM = (w & 3) * 32, wN = (w >> 2) * 64;
    uint32_t base = sb + st * 40960;
    const int arow = wM + (lane & 15);
    const int achk = (lane >> 4) * 16;             // k-chunk byte offset
    const int brow = wN + ((lane >> 4) ? 8 : 0) + (lane & 7);
    const int bchk = ((lane >> 3) & 1) * 16;

#pragma unroll
    for (int kk = 0; kk < 2; kk++) {
        const uint32_t kb = kk * 32;               // 16 bf16 = 32 bytes
        uint32_t a_hi[2][4], a_lo[2][4];
#pragma unroll
        for (int mt = 0; mt < 2; mt++) {
            uint32_t ad = base + (arow + mt * 16) * 80 + kb + achk;
            LDSM4(a_hi[mt], ad);
            LDSM4(a_lo[mt], ad + 10240);
        }
#pragma unroll
        for (int nb = 0; nb < 4; nb++) {
            uint32_t bd = base + 20480 + (brow + nb * 16) * 80 + kb + bchk;
            uint32_t bh[4], bl[4];
            LDSM4(bh, bd);
            LDSM4(bl, bd + 10240);
#pragma unroll
            for (int mt = 0; mt < 2; mt++) {
                MMA16816(acc[mt][nb * 2 + 0], a_hi[mt], bh[0], bh[1]);
                MMA16816(acc[mt][nb * 2 + 0], a_hi[mt], bl[0], bl[1]);
                MMA16816(acc[mt][nb * 2 + 0], a_lo[mt], bh[0], bh[1]);
                MMA16816(acc[mt][nb * 2 + 1], a_hi[mt], bh[2], bh[3]);
                MMA16816(acc[mt][nb * 2 + 1], a_hi[mt], bl[2], bl[3]);
                MMA16816(acc[mt][nb * 2 + 1], a_lo[mt], bh[2], bh[3]);
            }
        }
    }
}

__device__ __forceinline__ void gemm_mainloop(uint32_t sb, int m0, int nbase,
                                              float acc[2][8][4])
{
#pragma unroll
    for (int mt = 0; mt < 2; mt++)
#pragma unroll
        for (int nf = 0; nf < 8; nf++)
#pragma unroll
            for (int e = 0; e < 4; e++) acc[mt][nf][e] = 0.f;

    stage(sb, 0, m0, nbase, 0);
    for (int c = 0; c < 16; c++) {
        if (c < 15) {
            stage(sb, (c + 1) & 1, m0, nbase, (c + 1) * 32);
            asm volatile("cp.async.wait_group 1;" ::: "memory");
        } else {
            asm volatile("cp.async.wait_group 0;" ::: "memory");
        }
        __syncthreads();
        compute_chunk(sb, c & 1, acc);
        __syncthreads();
    }
}

// QKV projection: head-major scatter.
__global__ void __launch_bounds__(256, 2) mma_gemm_qkv()
{
    extern __shared__ char sm[];
    uint32_t sb = smem_u32(sm);
    const int m0 = blockIdx.y << 7;
    const int nbase = blockIdx.x << 7;     // 0..1535
    float acc[2][8][4];
    gemm_mainloop(sb, m0, nbase, acc);

    const int lane = threadIdx.x & 31, w = threadIdx.x >> 5;
    const int wM = (w & 3) * 32, wN = (w >> 2) * 64;
#pragma unroll
    for (int mt = 0; mt < 2; mt++) {
        int r0 = m0 + wM + mt * 16 + (lane >> 2);
        int b = r0 >> 11, s = r0 & (S_ - 1);
#pragma unroll
        for (int nb = 0; nb < 4; nb++) {
#pragma unroll
            for (int nf = 0; nf < 2; nf++) {
                float* c = acc[mt][nb * 2 + nf];
                int n = nbase + wN + nb * 16 + nf * 8 + (lane & 3) * 2;
                int mat = n >> 9, cc = n & 511;
                int h = cc >> 6, d = cc & 63;
                float* outp = (mat == 0) ? g_q : (mat == 1 ? g_k : g_v);
                long o0 = (((long)b * H_ + h) * S_ + s) * D_ + d;
                *(float2*)(outp + o0)          = make_float2(c[0], c[1]);
                *(float2*)(outp + o0 + 8 * D_) = make_float2(c[2], c[3]);
            }
        }
    }
}

// Output projection: row-major store to C.
__global__ void __launch_bounds__(256, 2) mma_gemm_out(float* __restrict__ C)
{
    extern __shared__ char sm[];
    uint32_t sb = smem_u32(sm);
    const int m0 = blockIdx.y << 7;
    const int nbase = blockIdx.x << 7;     // 0..511 within Wo rows
    float acc[2][8][4];
    gemm_mainloop(sb, m0, 3 * DM_ + nbase, acc);

    const int lane = threadIdx.x & 31, w = threadIdx.x >> 5;
    const int wM = (w & 3) * 32, wN = (w >> 2) * 64;
#pragma unroll
    for (int mt = 0; mt < 2; mt++) {
        int r0 = m0 + wM + mt * 16 + (lane >> 2);
#pragma unroll
        for (int nb = 0; nb < 4; nb++) {
#pragma unroll
            for (int nf = 0; nf < 2; nf++) {
                float* c = acc[mt][nb * 2 + nf];
                int n = nbase + wN + nb * 16 + nf * 8 + (lane & 3) * 2;
                *(float2*)(C + (long)r0 * DM_ + n)       = make_float2(c[0], c[1]);
                *(float2*)(C + (long)(r0 + 8) * DM_ + n) = make_float2(c[2], c[3]);
            }
        }
    }
}

// ---------------------------------------------------------------------------
// Sliding-window attention, f32x2 packed (unchanged — passed round 2).
// ---------------------------------------------------------------------------
#define ATT_SMEM_FLOATS (64*66 + 192*64 + 192*64)
#define ATT_SMEM_BYTES  (ATT_SMEM_FLOATS * 4)

__global__ void __launch_bounds__(256, 1) attn_k()
{
    extern __shared__ float smf[];
    float* Qs = smf;
    float* Ks = smf + 64 * 66;
    float* Vs = Ks + 192 * 64;
    float* Ss = smf;

    const int tid = threadIdx.x;
    const int s0 = blockIdx.x << 6;
    const int h  = blockIdx.y;
    const int b  = blockIdx.z;
    const int base = ((b * H_ + h) * S_) * D_;

#pragma unroll
    for (int it = 0; it < 4; it++) {
        int idx = tid + it * 256;
        int qq = idx >> 4;
        int dc = (idx & 15) << 2;
        float4 qv = *(const float4*)(g_q + base + (s0 + qq) * D_ + dc);
        Qs[qq * 66 + dc + 0] = qv.x;
        Qs[qq * 66 + dc + 1] = qv.y;
        Qs[qq * 66 + dc + 2] = qv.z;
        Qs[qq * 66 + dc + 3] = qv.w;
    }
#pragma unroll
    for (int it = 0; it < 12; it++) {
        int idx = tid + it * 256;
        int jr = idx >> 4;
        int dc = (idx & 15) << 2;
        int kg = s0 - (W_ - 1) + jr;
        float4 kv = make_float4(0.f, 0.f, 0.f, 0.f);
        float4 vv = make_float4(0.f, 0.f, 0.f, 0.f);
        if (kg >= 0) {
            kv = *(const float4*)(g_k + base + kg * D_ + dc);
            vv = *(const float4*)(g_v + base + kg * D_ + dc);
        }
        *(float4*)(Ks + jr * 64 + dc) = kv;
        *(float4*)(Vs + jr * 64 + dc) = vv;
    }
    __syncthreads();

    const int qg = tid & 15;
    const int jg = tid >> 4;
    const int jb = jg * 12;
    ull acc2[4][12];
#pragma unroll
    for (int r = 0; r < 4; r++)
#pragma unroll
        for (int u = 0; u < 12; u++) acc2[r][u] = 0ull;

#pragma unroll 4
    for (int d = 0; d < 64; d += 2) {
        ull qv[4];
#pragma unroll
        for (int r = 0; r < 4; r++)
            qv[r] = *(ull*)(&Qs[(qg + 16 * r) * 66 + d]);
#pragma unroll
        for (int u = 0; u < 12; u++) {
            ull kv = *(ull*)(&Ks[(jb + u) * 64 + d]);
            fma2(acc2[0][u], qv[0], kv);
            fma2(acc2[1][u], qv[1], kv);
            fma2(acc2[2][u], qv[2], kv);
            fma2(acc2[3][u], qv[3], kv);
        }
    }
    __syncthreads();

#pragma unroll
    for (int r = 0; r < 4; r++) {
        int i  = qg + 16 * r;
        int lo = (i > (W_ - 1) - s0) ? i : ((W_ - 1) - s0);
        int hi = i + (W_ - 1);
#pragma unroll
        for (int u = 0; u < 12; u++) {
            int j = jb + u;
            float2 f = unpk(acc2[r][u]);
            float sv = (f.x + f.y) * 0.125f;
            Ss[i * 193 + j] = (j >= lo && j <= hi) ? sv : -3.0e38f;
        }
    }
    __syncthreads();

    {
        const int w = tid >> 5, lane = tid & 31;
#pragma unroll
        for (int rr = 0; rr < 8; rr++) {
            float* row = Ss + ((w << 3) + rr) * 193;
            float m = -3.0e38f;
#pragma unroll
            for (int c = lane; c < 192; c += 32) m = fmaxf(m, row[c]);
#pragma unroll
            for (int msk = 16; msk >= 1; msk >>= 1)
                m = fmaxf(m, __shfl_xor_sync(0xffffffffu, m, msk));
            float ssum = 0.f;
#pragma unroll
            for (int c = lane; c < 192; c += 32) {
                float e = __expf(row[c] - m);
                row[c] = e;
                ssum += e;
            }
#pragma unroll
            for (int msk = 16; msk >= 1; msk >>= 1)
                ssum += __shfl_xor_sync(0xffffffffu, ssum, msk);
            float inv = 1.0f / ssum;
#pragma unroll
            for (int c = lane; c < 192; c += 32) row[c] *= inv;
        }
    }
    __syncthreads();

    {
        const int qg3 = tid & 15;
        const int dg  = tid >> 4;
        ull o2[4][2];
#pragma unroll
        for (int r = 0; r < 4; r++) { o2[r][0] = 0ull; o2[r][1] = 0ull; }

#pragma unroll 4
        for (int j = 0; j < 192; j++) {
            float4 vv = *(float4*)(Vs + j * 64 + dg * 4);
            ull v0 = pack2(vv.x, vv.y);
            ull v1 = pack2(vv.z, vv.w);
#pragma unroll
            for (int r = 0; r < 4; r++) {
                float p = Ss[(qg3 + 16 * r) * 193 + j];
                ull pp = pack2(p, p);
                fma2(o2[r][0], pp, v0);
                fma2(o2[r][1], pp, v1);
            }
        }
#pragma unroll
        for (int r = 0; r < 4; r++) {
            int q = qg3 + 16 * r;
            float2 p0 = unpk(o2[r][0]);
            float2 p1 = unpk(o2[r][1]);
            float4 ov = make_float4(p0.x, p0.y, p1.x, p1.y);
            *(float4*)(g_attn + (b * S_ + s0 + q) * DM_ + h * D_ + dg * 4) = ov;
        }
    }
}

// ---------------------------------------------------------------------------
extern "C" void kernel_launch(void* const* d_in, const int* in_sizes, int n_in,
                              void* d_out, int out_size)
{
    const float* x  = (const float*)d_in[0];
    const float* Wq = (const float*)d_in[1];
    const float* Wk = (const float*)d_in[2];
    const float* Wv = (const float*)d_in[3];
    const float* Wo = (const float*)d_in[4];
    float* out = (float*)d_out;

    cudaFuncSetAttribute(mma_gemm_qkv, cudaFuncAttributeMaxDynamicSharedMemorySize, GSM_BYTES);
    cudaFuncSetAttribute(mma_gemm_out, cudaFuncAttributeMaxDynamicSharedMemorySize, GSM_BYTES);
    cudaFuncSetAttribute(attn_k, cudaFuncAttributeMaxDynamicSharedMemorySize, ATT_SMEM_BYTES);

    // 1. split X into bf16 hi/lo
    conv_split_k<<<(B_*S_*DM_) / 1024, 256>>>(x, 0);
    // 2. transpose + split weights
    conv_w_k<<<dim3(16, 16, 4), 256>>>(Wq, Wk, Wv, Wo);
    // 3. QKV via tensor cores (mma.sync)
    mma_gemm_qkv<<<dim3(12, 32), 256, GSM_BYTES>>>();
    // 4. sliding-window attention
    attn_k<<<dim3(S_ / 64, H_, B_), 256, ATT_SMEM_BYTES>>>();
    // 5. split attention output
    conv_split_k<<<(B_*S_*DM_) / 1024, 256>>>(nullptr, 1);
    // 6. output projection via tensor cores
    mma_gemm_out<<<dim3(4, 32), 256, GSM_BYTES>>>(out);
}